// round 14
// baseline (speedup 1.0000x reference)
#include <cuda_runtime.h>
#include <cuda_fp16.h>
#include <math.h>

#define BB 4
#define T 4096
#define DM 1024
#define NROWS (BB * T)          // 16384
#define NOUT (3 * DM)           // 3072

// ---------------- scratch ----------------
__device__ __half g_Xh[(size_t)NROWS * DM];        // fp16 input, PERMUTED c' = h*64+q
__device__ __half g_Wc2[(size_t)NOUT * 128];       // compact block-diag weights
__device__ __half g_Qh[(size_t)NROWS * DM];        // permuted c' = h*64+d
__device__ __half g_Kh[(size_t)NROWS * DM];        // permuted
__device__ __half g_Vp[(size_t)NROWS * DM];        // V permuted (proj output)
__device__ __half g_Vh[(size_t)NROWS * DM];        // V ORIGINAL layout c = d*16+h
__device__ __half g_Ph[(size_t)BB * T * T];        // fp16 unnormalized probs
__device__ float  g_Sum[NROWS];                    // row sums of exp(s)
__device__ float  g_invf[512];                     // rope inverse frequencies
__device__ float2 g_cs[(size_t)8 * T * 64];        // [hp][t][d] (cos,sin)
__device__ unsigned g_ticket;                      // pv work-stealing counter

// ---------------- helpers ----------------
__device__ __forceinline__ unsigned h2exp2(float lo, float hi) {
    unsigned d, r;
    asm("cvt.rn.f16x2.f32 %0, %1, %2;" : "=r"(d) : "f"(hi), "f"(lo));
    asm("ex2.approx.f16x2 %0, %1;" : "=r"(r) : "r"(d));
    return r;
}

__device__ __forceinline__ void cpa16(void* dst, const void* src) {
    unsigned d = (unsigned)__cvta_generic_to_shared(dst);
    asm volatile("cp.async.cg.shared.global [%0], [%1], 16;" :: "r"(d), "l"(src));
}
__device__ __forceinline__ void cpa_commit() {
    asm volatile("cp.async.commit_group;" ::: "memory");
}
template <int N>
__device__ __forceinline__ void cpa_wait() {
    asm volatile("cp.async.wait_group %0;" :: "n"(N) : "memory");
}

__device__ __forceinline__ void ldsm4(unsigned& r0, unsigned& r1, unsigned& r2,
                                      unsigned& r3, unsigned addr) {
    asm volatile("ldmatrix.sync.aligned.m8n8.x4.shared.b16 {%0,%1,%2,%3}, [%4];"
        : "=r"(r0), "=r"(r1), "=r"(r2), "=r"(r3) : "r"(addr));
}
__device__ __forceinline__ void ldsm4t(unsigned& r0, unsigned& r1, unsigned& r2,
                                       unsigned& r3, unsigned addr) {
    asm volatile("ldmatrix.sync.aligned.m8n8.x4.trans.shared.b16 {%0,%1,%2,%3}, [%4];"
        : "=r"(r0), "=r"(r1), "=r"(r2), "=r"(r3) : "r"(addr));
}

__device__ __forceinline__ void mma_f16(float* c, const unsigned* a, const unsigned* b) {
    asm volatile(
        "mma.sync.aligned.m16n8k16.row.col.f32.f16.f16.f32 "
        "{%0,%1,%2,%3}, {%4,%5,%6,%7}, {%8,%9}, {%0,%1,%2,%3};\n"
        : "+f"(c[0]), "+f"(c[1]), "+f"(c[2]), "+f"(c[3])
        : "r"(a[0]), "r"(a[1]), "r"(a[2]), "r"(a[3]), "r"(b[0]), "r"(b[1]));
}

#define PXS(a) ((a) ^ (((a) >> 5) & 28))   // smem swizzle for permute

// =========================================================================
// Kernel 1: permute x -> fp16 head-major, init g_Sum, g_invf, g_ticket.
// =========================================================================
__global__ void __launch_bounds__(256)
permute_kernel(const float* __restrict__ x)
{
    __shared__ float sm[4][1024];
    const int row0 = blockIdx.x * 4;
    const int tid = threadIdx.x;
    const int c = tid * 4;

#pragma unroll
    for (int rr = 0; rr < 4; rr++)
        *(float4*)&sm[rr][PXS(c)] = *(const float4*)&x[(size_t)(row0 + rr) * DM + c];
    __syncthreads();

    const int h = c >> 6, q = c & 63;
#pragma unroll
    for (int rr = 0; rr < 4; rr++) {
        float v0 = sm[rr][PXS(q * 16 + h)];
        float v1 = sm[rr][PXS((q + 1) * 16 + h)];
        float v2 = sm[rr][PXS((q + 2) * 16 + h)];
        float v3 = sm[rr][PXS((q + 3) * 16 + h)];
        __half2 h0 = __floats2half2_rn(v0, v1);
        __half2 h1 = __floats2half2_rn(v2, v3);
        uint2 pk;
        pk.x = *(unsigned*)&h0;
        pk.y = *(unsigned*)&h1;
        *(uint2*)&g_Xh[(size_t)(row0 + rr) * DM + c] = pk;
    }
    if (tid < 4) g_Sum[row0 + tid] = 0.f;
    if (blockIdx.x == 0) {
        if (tid == 0) g_ticket = 0u;
        g_invf[tid]       = (float)pow(10000.0, -(double)tid / 512.0);
        g_invf[tid + 256] = (float)pow(10000.0, -(double)(tid + 256) / 512.0);
    }
}

// =========================================================================
// Kernel 2: cos/sin table, layout [hp][t][d]. grid T, block 512.
// =========================================================================
__global__ void __launch_bounds__(512)
table_kernel()
{
    const int t = blockIdx.x;
    const int i = threadIdx.x;
    const int hp = i >> 6, d = i & 63;
    const int p = d * 8 + hp;
    float s, c;
    sincosf((float)t * g_invf[p], &s, &c);
    g_cs[((size_t)hp * T + t) * 64 + d] = make_float2(c, s);
}

// =========================================================================
// Kernel 3: compact block-diag weights Wc2[n''][128].
// =========================================================================
__global__ void __launch_bounds__(128)
fillw_kernel(const float* __restrict__ wq,
             const float* __restrict__ wk,
             const float* __restrict__ wv)
{
    const int n = blockIdx.x;
    const int m = n >> 10;
    const int rem = n & 1023;
    const int h = rem >> 6, d = rem & 63;
    const int k = threadIdx.x;
    const float* w = (m == 0) ? wq : (m == 1) ? wk : wv;
    __half v = __float2half_rn(0.f);
    if ((k >> 6) == (h & 1)) {
        int q = k & 63;
        v = __float2half_rn(w[(q * 64 + d) * 16 + h]);
    }
    g_Wc2[(size_t)n * 128 + k] = v;
}

// =========================================================================
// Kernel 4: QKV projection v2 (one CTA: Q, K, V for one slice/row-tile).
// cs loads widened to float4. grid (8, 128), block 256, dyn smem 96KB.
// =========================================================================
__device__ __forceinline__ void proj_mma16(float acc[16][4], unsigned ab, unsigned bb,
                                           int a_row, int a_du, int b_row, int b_du,
                                           int lx)
{
#pragma unroll
    for (int kk = 0; kk < 8; kk++) {
        unsigned af[4], bf[16][2];
        ldsm4(af[0], af[1], af[2], af[3],
              ab + (unsigned)(a_row * 256 + (((2 * kk + a_du) ^ lx) << 4)));
#pragma unroll
        for (int p = 0; p < 8; p++)
            ldsm4(bf[2 * p][0], bf[2 * p][1], bf[2 * p + 1][0], bf[2 * p + 1][1],
                  bb + (unsigned)((b_row + 16 * p) * 256 + (((2 * kk + b_du) ^ lx) << 4)));
#pragma unroll
        for (int nt = 0; nt < 16; nt++) mma_f16(acc[nt], af, bf[nt]);
    }
}

__global__ void __launch_bounds__(256, 2)
proj_kernel()
{
    extern __shared__ __align__(128) char smc[];

    const int o = blockIdx.x * 128;
    const int i0 = blockIdx.y * 128;
    const int hp = o >> 7;

    const int tid = threadIdx.x;
    const int wid = tid >> 5, lane = tid & 31;
    const int group = lane >> 2, tid4 = lane & 3;

    const unsigned sb = (unsigned)__cvta_generic_to_shared(smc);

#pragma unroll
    for (int l = 0; l < 8; l++) {
        int idx = tid + l * 256;
        int r = idx >> 4, u = idx & 15;
        int dst = r * 256 + ((u ^ (r & 7)) << 4);
        cpa16(smc + dst,         &g_Xh[(size_t)(i0 + r) * DM + o + u * 8]);
        cpa16(smc + 32768 + dst, &g_Wc2[(size_t)(o + r) * 128 + u * 8]);
    }
    cpa_commit();
#pragma unroll
    for (int l = 0; l < 8; l++) {
        int idx = tid + l * 256;
        int r = idx >> 4, u = idx & 15;
        int dst = r * 256 + ((u ^ (r & 7)) << 4);
        cpa16(smc + 65536 + dst, &g_Wc2[(size_t)(1024 + o + r) * 128 + u * 8]);
    }
    cpa_commit();

    const int lx = lane & 7;
    const int a_row = (wid << 4) + (lane & 15);
    const int a_du = lane >> 4;
    const int b_row = (lane & 7) + ((lane >> 4) << 3);
    const int b_du = (lane >> 3) & 1;

    const int r0 = (wid << 4) + group;
    const size_t rowA = (size_t)(i0 + r0) * DM + o;
    const size_t rowB = (size_t)(i0 + r0 + 8) * DM + o;
    const float2* csA = g_cs + ((size_t)hp * T + ((i0 + r0) & (T - 1))) * 64;
    const float2* csB = g_cs + ((size_t)hp * T + ((i0 + r0 + 8) & (T - 1))) * 64;

    float acc[16][4];

    // ---- m = 0 (Q) ----
    cpa_wait<1>();
    __syncthreads();
#pragma unroll
    for (int nt = 0; nt < 16; nt++)
#pragma unroll
        for (int r = 0; r < 4; r++) acc[nt][r] = 0.f;
    proj_mma16(acc, sb, sb + 32768, a_row, a_du, b_row, b_du, lx);
    __syncthreads();
#pragma unroll
    for (int l = 0; l < 8; l++) {
        int idx = tid + l * 256;
        int r = idx >> 4, u = idx & 15;
        int dst = r * 256 + ((u ^ (r & 7)) << 4);
        cpa16(smc + 32768 + dst, &g_Wc2[(size_t)(2048 + o + r) * 128 + u * 8]);
    }
    cpa_commit();
#pragma unroll
    for (int nt = 0; nt < 8; nt++) {
        int c = nt * 8 + tid4 * 2;
        float4 cA = *(const float4*)&csA[c];   // (cos0,sin0,cos1,sin1)
        float a0 = acc[nt][0], a1 = acc[nt][1];
        float b0 = acc[nt + 8][0], b1 = acc[nt + 8][1];
        *(__half2*)&g_Qh[rowA + c] =
            __floats2half2_rn(a0 * cA.x - b0 * cA.y, a1 * cA.z - b1 * cA.w);
        *(__half2*)&g_Qh[rowA + 64 + c] =
            __floats2half2_rn(a0 * cA.y + b0 * cA.x, a1 * cA.w + b1 * cA.z);
        float4 cB = *(const float4*)&csB[c];
        float a2 = acc[nt][2], a3 = acc[nt][3];
        float b2 = acc[nt + 8][2], b3 = acc[nt + 8][3];
        *(__half2*)&g_Qh[rowB + c] =
            __floats2half2_rn(a2 * cB.x - b2 * cB.y, a3 * cB.z - b3 * cB.w);
        *(__half2*)&g_Qh[rowB + 64 + c] =
            __floats2half2_rn(a2 * cB.y + b2 * cB.x, a3 * cB.w + b3 * cB.z);
    }

    // ---- m = 1 (K) ----
    cpa_wait<1>();
    __syncthreads();
#pragma unroll
    for (int nt = 0; nt < 16; nt++)
#pragma unroll
        for (int r = 0; r < 4; r++) acc[nt][r] = 0.f;
    proj_mma16(acc, sb, sb + 65536, a_row, a_du, b_row, b_du, lx);
#pragma unroll
    for (int nt = 0; nt < 8; nt++) {
        int c = nt * 8 + tid4 * 2;
        float4 cA = *(const float4*)&csA[c];
        float a0 = acc[nt][0], a1 = acc[nt][1];
        float b0 = acc[nt + 8][0], b1 = acc[nt + 8][1];
        *(__half2*)&g_Kh[rowA + c] =
            __floats2half2_rn(a0 * cA.x - b0 * cA.y, a1 * cA.z - b1 * cA.w);
        *(__half2*)&g_Kh[rowA + 64 + c] =
            __floats2half2_rn(a0 * cA.y + b0 * cA.x, a1 * cA.w + b1 * cA.z);
        float4 cB = *(const float4*)&csB[c];
        float a2 = acc[nt][2], a3 = acc[nt][3];
        float b2 = acc[nt + 8][2], b3 = acc[nt + 8][3];
        *(__half2*)&g_Kh[rowB + c] =
            __floats2half2_rn(a2 * cB.x - b2 * cB.y, a3 * cB.z - b3 * cB.w);
        *(__half2*)&g_Kh[rowB + 64 + c] =
            __floats2half2_rn(a2 * cB.y + b2 * cB.x, a3 * cB.w + b3 * cB.z);
    }

    // ---- m = 2 (V) ----
    cpa_wait<0>();
    __syncthreads();
#pragma unroll
    for (int nt = 0; nt < 16; nt++)
#pragma unroll
        for (int r = 0; r < 4; r++) acc[nt][r] = 0.f;
    proj_mma16(acc, sb, sb + 32768, a_row, a_du, b_row, b_du, lx);
#pragma unroll
    for (int nt = 0; nt < 8; nt++) {
        int c = nt * 8 + tid4 * 2;
        *(__half2*)&g_Vp[rowA + c]      = __floats2half2_rn(acc[nt][0], acc[nt][1]);
        *(__half2*)&g_Vp[rowA + 64 + c] = __floats2half2_rn(acc[nt + 8][0], acc[nt + 8][1]);
        *(__half2*)&g_Vp[rowB + c]      = __floats2half2_rn(acc[nt][2], acc[nt][3]);
        *(__half2*)&g_Vp[rowB + 64 + c] = __floats2half2_rn(acc[nt + 8][2], acc[nt + 8][3]);
    }
}

// =========================================================================
// Kernel 4b: V layout transform  c'=h*64+d  ->  c=d*16+h.
// =========================================================================
__global__ void __launch_bounds__(256)
vtrans_kernel()
{
    __shared__ __half sm[8][1092];
    const int r0 = blockIdx.x * 8;
    const int tid = threadIdx.x;

#pragma unroll
    for (int k = 0; k < 16; k++) {
        int idx = k * 256 + tid;
        int rr = idx >> 9;
        int ui = idx & 511;
        unsigned v = ((const unsigned*)&g_Vp[(size_t)(r0 + rr) * DM])[ui];
        int h = ui >> 5;
        int dw = ui & 31;
        ((unsigned*)&sm[rr][h * 68])[dw] = v;
    }
    __syncthreads();

#pragma unroll
    for (int k = 0; k < 16; k++) {
        int idx = k * 256 + tid;
        int rr = idx >> 9;
        int j = idx & 511;
        int c = j * 2;
        int h0 = c & 15,      d0 = c >> 4;
        int h1 = (c + 1) & 15, d1 = (c + 1) >> 4;
        __half lo = sm[rr][h0 * 68 + d0];
        __half hi = sm[rr][h1 * 68 + d1];
        *(__half2*)&g_Vh[(size_t)(r0 + rr) * DM + c] = __halves2half2(lo, hi);
    }
}

// =========================================================================
// Shared GEMM machinery (64-col K-chunks).
// =========================================================================
#define GK_STAGE_B 32768

__device__ __forceinline__ void gk_load(char* st, const __half* Ab, const __half* Bb,
                                        int kc, int tid)
{
#pragma unroll
    for (int l = 0; l < 4; l++) {
        int idx = tid + l * 256;
        int r = idx >> 3, u = idx & 7;
        int dst = r * 128 + ((u ^ (r & 7)) << 4);
        cpa16(st + dst,         &Ab[(size_t)r * DM + kc + u * 8]);
        cpa16(st + 16384 + dst, &Bb[(size_t)r * DM + kc + u * 8]);
    }
}

__device__ __forceinline__ void gk_mma(float acc[2][8][4], unsigned qb, unsigned kb,
                                       int m0, int n0, int lane)
{
    const int lx = lane & 7;
    const int a_row = m0 + (lane & 7) + (lane & 8);
    const int a_du = lane >> 4;
    const int b_row = n0 + (lane & 7) + ((lane >> 4) << 3);
    const int b_du = (lane >> 3) & 1;

#pragma unroll
    for (int kk = 0; kk < 4; kk++) {
        unsigned af[2][4], bf[8][2];
#pragma unroll
        for (int mt = 0; mt < 2; mt++)
            ldsm4(af[mt][0], af[mt][1], af[mt][2], af[mt][3],
                  qb + (unsigned)((a_row + mt * 16) * 128 + (((2 * kk + a_du) ^ lx) << 4)));
#pragma unroll
        for (int p = 0; p < 4; p++)
            ldsm4(bf[2 * p][0], bf[2 * p][1], bf[2 * p + 1][0], bf[2 * p + 1][1],
                  kb + (unsigned)((b_row + 16 * p) * 128 + (((2 * kk + b_du) ^ lx) << 4)));
#pragma unroll
        for (int mt = 0; mt < 2; mt++)
#pragma unroll
            for (int nt = 0; nt < 8; nt++) mma_f16(acc[mt][nt], af[mt], bf[nt]);
    }
}

// =========================================================================
// Kernel 5: P = exp(gamma * Q K^T) (causal), row sums via atomicAdd.
// grid (528, B), block 256, dyn smem 96KB
// =========================================================================
__global__ void __launch_bounds__(256, 2)
qk_kernel()
{
    extern __shared__ __align__(128) char smc[];

    const int b = blockIdx.y;
    const int xid = blockIdx.x;
    int ti = (int)((sqrtf(8.f * xid + 1.f) - 1.f) * 0.5f);
    while ((ti + 1) * (ti + 2) / 2 <= xid) ti++;
    while (ti * (ti + 1) / 2 > xid) ti--;
    const int tj = xid - ti * (ti + 1) / 2;
    const int i0 = ti * 128, j0 = tj * 128;

    const __half* Qb = g_Qh + (size_t)(b * T + i0) * DM;
    const __half* Kb = g_Kh + (size_t)(b * T + j0) * DM;

    const int tid = threadIdx.x;
    const int wid = tid >> 5, lane = tid & 31;
    const int group = lane >> 2, tid4 = lane & 3;
    const int m0 = (wid >> 1) * 32, n0 = (wid & 1) * 64;

    const unsigned sb = (unsigned)__cvta_generic_to_shared(smc);

    float acc[2][8][4];
#pragma unroll
    for (int mt = 0; mt < 2; mt++)
#pragma unroll
        for (int nt = 0; nt < 8; nt++)
#pragma unroll
            for (int r = 0; r < 4; r++) acc[mt][nt][r] = 0.f;

    const int NK = 16;
    gk_load(smc,              Qb, Kb, 0,  tid); cpa_commit();
    gk_load(smc + GK_STAGE_B, Qb, Kb, 64, tid); cpa_commit();

    for (int c = 0; c < NK; c++) {
        if (c + 1 < NK) { cpa_wait<1>(); } else { cpa_wait<0>(); }
        __syncthreads();
        if (c + 2 < NK) {
            gk_load(smc + ((c + 2) % 3) * GK_STAGE_B, Qb, Kb, (c + 2) * 64, tid);
            cpa_commit();
        }
        unsigned base = sb + (unsigned)((c % 3) * GK_STAGE_B);
        gk_mma(acc, base, base + 16384, m0, n0, lane);
    }

    const float GL = 0.03125f * 1.44269504f;
    const bool diag = (ti == tj);

#pragma unroll
    for (int mt = 0; mt < 2; mt++) {
        int rg = i0 + m0 + mt * 16 + group;
        float sum0 = 0.f, sum1 = 0.f;
#pragma unroll
        for (int nt = 0; nt < 8; nt++) {
            int cg = j0 + n0 + nt * 8 + tid4 * 2;
            float t0 = acc[mt][nt][0] * GL;
            float t1 = acc[mt][nt][1] * GL;
            float t2 = acc[mt][nt][2] * GL;
            float t3 = acc[mt][nt][3] * GL;
            if (diag) {
                if (cg     > rg)     t0 = -60000.f;
                if (cg + 1 > rg)     t1 = -60000.f;
                if (cg     > rg + 8) t2 = -60000.f;
                if (cg + 1 > rg + 8) t3 = -60000.f;
            }
            unsigned p01 = h2exp2(t0, t1);
            unsigned p23 = h2exp2(t2, t3);
            float2 f0 = __half22float2(*(__half2*)&p01);
            float2 f1 = __half22float2(*(__half2*)&p23);
            sum0 += f0.x + f0.y;
            sum1 += f1.x + f1.y;
            *(unsigned*)&g_Ph[(size_t)(b * T + rg) * T + cg]     = p01;
            *(unsigned*)&g_Ph[(size_t)(b * T + rg + 8) * T + cg] = p23;
        }
        sum0 += __shfl_xor_sync(0xffffffffu, sum0, 1);
        sum0 += __shfl_xor_sync(0xffffffffu, sum0, 2);
        sum1 += __shfl_xor_sync(0xffffffffu, sum1, 1);
        sum1 += __shfl_xor_sync(0xffffffffu, sum1, 2);
        if (tid4 == 0) {
            atomicAdd(&g_Sum[b * T + rg],     sum0);
            atomicAdd(&g_Sum[b * T + rg + 8], sum1);
        }
    }
}

// =========================================================================
// Kernel 6: Y = (P V) / g_Sum[row] — PERSISTENT CTAs + work stealing.
// 1024 tiles ordered heavy-first (mi descending). grid 296, block 256.
// =========================================================================
#define PV_STAGE_B 32768

__device__ __forceinline__ void pv_load(char* st, const __half* Pb, const __half* Vb,
                                        int kc, int tid)
{
#pragma unroll
    for (int l = 0; l < 4; l++) {
        int idx = tid + l * 256;
        {
            int r = idx >> 3, u = idx & 7;
            cpa16(st + r * 128 + ((u ^ (r & 7)) << 4),
                  &Pb[(size_t)r * T + kc + u * 8]);
        }
        {
            int r = idx >> 4, u = idx & 15;
            cpa16(st + 16384 + r * 256 + ((u ^ (r & 7)) << 4),
                  &Vb[(size_t)(kc + r) * DM + u * 8]);
        }
    }
}

__device__ __forceinline__ void pv_mma(float acc[2][8][4], unsigned pb, unsigned vb,
                                       int m0, int n0, int lane)
{
    const int lx = lane & 7;
    const int a_row = m0 + (lane & 7) + (lane & 8);
    const int a_du = lane >> 4;
    const int v_row = (lane & 7) + (lane & 8);
    const int v_du = lane >> 4;
    const int un0 = n0 >> 3;

#pragma unroll
    for (int kk = 0; kk < 4; kk++) {
        unsigned af[2][4], bf[8][2];
#pragma unroll
        for (int mt = 0; mt < 2; mt++)
            ldsm4(af[mt][0], af[mt][1], af[mt][2], af[mt][3],
                  pb + (unsigned)((a_row + mt * 16) * 128 + (((2 * kk + a_du) ^ lx) << 4)));
        const int vr = 16 * kk + v_row;
#pragma unroll
        for (int p = 0; p < 4; p++)
            ldsm4t(bf[2 * p][0], bf[2 * p][1], bf[2 * p + 1][0], bf[2 * p + 1][1],
                   vb + (unsigned)(vr * 256 + (((un0 + 2 * p + v_du) ^ lx) << 4)));
#pragma unroll
        for (int mt = 0; mt < 2; mt++)
#pragma unroll
            for (int nt = 0; nt < 8; nt++) mma_f16(acc[mt][nt], af[mt], bf[nt]);
    }
}

__global__ void __launch_bounds__(256, 2)
pv_kernel(float* __restrict__ out)
{
    extern __shared__ __align__(128) char smc[];
    __shared__ unsigned s_tile;

    const int tid = threadIdx.x;
    const int wid = tid >> 5, lane = tid & 31;
    const int group = lane >> 2, tid4 = lane & 3;
    const int m0 = (wid >> 1) * 32, n0 = (wid & 1) * 64;
    const unsigned sb = (unsigned)__cvta_generic_to_shared(smc);

    for (;;) {
        __syncthreads();             // protect smem + s_tile reuse
        if (tid == 0) s_tile = atomicAdd(&g_ticket, 1u);
        __syncthreads();
        const unsigned t = s_tile;
        if (t >= 1024u) return;

        // decode: heavy-first (mi descending), ni/b interleaved
        const int mi = 31 - (int)(t >> 5);
        const int r5 = (int)(t & 31u);
        const int ni = r5 >> 2;
        const int b = r5 & 3;
        const int i0 = mi * 128, n0c = ni * 128;

        const __half* Pb = g_Ph + (size_t)(b * T + i0) * T;
        const __half* Vb = g_Vh + (size_t)(b * T) * DM + n0c;

        float acc[2][8][4];
#pragma unroll
        for (int mt = 0; mt < 2; mt++)
#pragma unroll
            for (int nt = 0; nt < 8; nt++)
#pragma unroll
                for (int r = 0; r < 4; r++) acc[mt][nt][r] = 0.f;

        const int nk = (mi + 1) * 2;

        pv_load(smc,              Pb, Vb, 0,  tid); cpa_commit();
        pv_load(smc + PV_STAGE_B, Pb, Vb, 64, tid); cpa_commit();

        for (int c = 0; c < nk; c++) {
            if (c + 1 < nk) { cpa_wait<1>(); } else { cpa_wait<0>(); }
            __syncthreads();
            if (c + 2 < nk) {
                pv_load(smc + ((c + 2) % 3) * PV_STAGE_B, Pb, Vb, (c + 2) * 64, tid);
                cpa_commit();
            }
            unsigned base = sb + (unsigned)((c % 3) * PV_STAGE_B);
            pv_mma(acc, base, base + 16384, m0, n0, lane);
        }

        const float* sump = g_Sum + (size_t)b * T + i0;
#pragma unroll
        for (int mt = 0; mt < 2; mt++) {
            int rloc = m0 + mt * 16 + group;
            float inva = 1.f / sump[rloc];
            float invb = 1.f / sump[rloc + 8];
#pragma unroll
            for (int nt = 0; nt < 8; nt++) {
                int rg = i0 + rloc;
                int cg = n0c + n0 + nt * 8 + tid4 * 2;
                *(float2*)&out[(size_t)(b * T + rg) * DM + cg] =
                    make_float2(acc[mt][nt][0] * inva, acc[mt][nt][1] * inva);
                *(float2*)&out[(size_t)(b * T + rg + 8) * DM + cg] =
                    make_float2(acc[mt][nt][2] * invb, acc[mt][nt][3] * invb);
            }
        }
    }
}

// =========================================================================
extern "C" void kernel_launch(void* const* d_in, const int* in_sizes, int n_in,
                              void* d_out, int out_size)
{
    const float* x  = (const float*)d_in[0];
    const float* wq = (const float*)d_in[1];
    const float* wk = (const float*)d_in[2];
    const float* wv = (const float*)d_in[3];
    float* out = (float*)d_out;

    cudaFuncSetAttribute(proj_kernel,
                         cudaFuncAttributeMaxDynamicSharedMemorySize, 98304);
    cudaFuncSetAttribute(qk_kernel,
                         cudaFuncAttributeMaxDynamicSharedMemorySize, 3 * GK_STAGE_B);
    cudaFuncSetAttribute(pv_kernel,
                         cudaFuncAttributeMaxDynamicSharedMemorySize, 3 * PV_STAGE_B);

    permute_kernel<<<4096, 256>>>(x);
    table_kernel<<<T, 512>>>();
    fillw_kernel<<<NOUT, 128>>>(wq, wk, wv);
    proj_kernel<<<dim3(8, 128), 256, 98304>>>();
    vtrans_kernel<<<NROWS / 8, 256>>>();
    qk_kernel<<<dim3(528, BB), 256, 3 * GK_STAGE_B>>>();
    pv_kernel<<<296, 256, 3 * PV_STAGE_B>>>(out);
}

// round 15
// speedup vs baseline: 1.4364x; 1.4364x over previous
#include <cuda_runtime.h>
#include <cuda_fp16.h>
#include <math.h>

#define BB 4
#define T 4096
#define DM 1024
#define NROWS (BB * T)          // 16384
#define NOUT (3 * DM)           // 3072

// ---------------- scratch ----------------
__device__ __half g_Xh[(size_t)NROWS * DM];        // fp16 input, PERMUTED c' = h*64+q
__device__ __half g_Wc2[(size_t)NOUT * 128];       // compact block-diag weights
__device__ __half g_Qh[(size_t)NROWS * DM];        // permuted c' = h*64+d
__device__ __half g_Kh[(size_t)NROWS * DM];        // permuted
__device__ __half g_Vh[(size_t)NROWS * DM];        // V ORIGINAL layout c = d*16+h
__device__ __half g_Ph[(size_t)BB * T * T];        // fp16 unnormalized probs
__device__ float  g_Sum[NROWS];                    // row sums of exp(s)
__device__ float  g_invf[512];                     // rope inverse frequencies
__device__ float2 g_cs[(size_t)8 * T * 64];        // [hp][t][d] (cos,sin)

// ---------------- helpers ----------------
__device__ __forceinline__ unsigned h2exp2(float lo, float hi) {
    unsigned d, r;
    asm("cvt.rn.f16x2.f32 %0, %1, %2;" : "=r"(d) : "f"(hi), "f"(lo));
    asm("ex2.approx.f16x2 %0, %1;" : "=r"(r) : "r"(d));
    return r;
}

__device__ __forceinline__ void cpa16(void* dst, const void* src) {
    unsigned d = (unsigned)__cvta_generic_to_shared(dst);
    asm volatile("cp.async.cg.shared.global [%0], [%1], 16;" :: "r"(d), "l"(src));
}
__device__ __forceinline__ void cpa_commit() {
    asm volatile("cp.async.commit_group;" ::: "memory");
}
template <int N>
__device__ __forceinline__ void cpa_wait() {
    asm volatile("cp.async.wait_group %0;" :: "n"(N) : "memory");
}

__device__ __forceinline__ void ldsm4(unsigned& r0, unsigned& r1, unsigned& r2,
                                      unsigned& r3, unsigned addr) {
    asm volatile("ldmatrix.sync.aligned.m8n8.x4.shared.b16 {%0,%1,%2,%3}, [%4];"
        : "=r"(r0), "=r"(r1), "=r"(r2), "=r"(r3) : "r"(addr));
}
__device__ __forceinline__ void ldsm4t(unsigned& r0, unsigned& r1, unsigned& r2,
                                       unsigned& r3, unsigned addr) {
    asm volatile("ldmatrix.sync.aligned.m8n8.x4.trans.shared.b16 {%0,%1,%2,%3}, [%4];"
        : "=r"(r0), "=r"(r1), "=r"(r2), "=r"(r3) : "r"(addr));
}

__device__ __forceinline__ void mma_f16(float* c, const unsigned* a, const unsigned* b) {
    asm volatile(
        "mma.sync.aligned.m16n8k16.row.col.f32.f16.f16.f32 "
        "{%0,%1,%2,%3}, {%4,%5,%6,%7}, {%8,%9}, {%0,%1,%2,%3};\n"
        : "+f"(c[0]), "+f"(c[1]), "+f"(c[2]), "+f"(c[3])
        : "r"(a[0]), "r"(a[1]), "r"(a[2]), "r"(a[3]), "r"(b[0]), "r"(b[1]));
}

#define PXS(a) ((a) ^ (((a) >> 5) & 28))   // smem swizzle for permute

// =========================================================================
// Kernel 1: permute x -> fp16 head-major (c' = h*64+q), init g_Sum, g_invf.
// =========================================================================
__global__ void __launch_bounds__(256)
permute_kernel(const float* __restrict__ x)
{
    __shared__ float sm[4][1024];
    const int row0 = blockIdx.x * 4;
    const int tid = threadIdx.x;
    const int c = tid * 4;

#pragma unroll
    for (int rr = 0; rr < 4; rr++)
        *(float4*)&sm[rr][PXS(c)] = *(const float4*)&x[(size_t)(row0 + rr) * DM + c];
    __syncthreads();

    const int h = c >> 6, q = c & 63;
#pragma unroll
    for (int rr = 0; rr < 4; rr++) {
        float v0 = sm[rr][PXS(q * 16 + h)];
        float v1 = sm[rr][PXS((q + 1) * 16 + h)];
        float v2 = sm[rr][PXS((q + 2) * 16 + h)];
        float v3 = sm[rr][PXS((q + 3) * 16 + h)];
        __half2 h0 = __floats2half2_rn(v0, v1);
        __half2 h1 = __floats2half2_rn(v2, v3);
        uint2 pk;
        pk.x = *(unsigned*)&h0;
        pk.y = *(unsigned*)&h1;
        *(uint2*)&g_Xh[(size_t)(row0 + rr) * DM + c] = pk;
    }
    if (tid < 4) g_Sum[row0 + tid] = 0.f;
    if (blockIdx.x == 0) {
        g_invf[tid]       = (float)pow(10000.0, -(double)tid / 512.0);
        g_invf[tid + 256] = (float)pow(10000.0, -(double)(tid + 256) / 512.0);
    }
}

// =========================================================================
// Kernel 2: cos/sin table, layout [hp][t][d]. grid T, block 512.
// =========================================================================
__global__ void __launch_bounds__(512)
table_kernel()
{
    const int t = blockIdx.x;
    const int i = threadIdx.x;
    const int hp = i >> 6, d = i & 63;
    const int p = d * 8 + hp;
    float s, c;
    sincosf((float)t * g_invf[p], &s, &c);
    g_cs[((size_t)hp * T + t) * 64 + d] = make_float2(c, s);
}

// =========================================================================
// Kernel 3: compact block-diag weights Wc2[n''][128].
// =========================================================================
__global__ void __launch_bounds__(128)
fillw_kernel(const float* __restrict__ wq,
             const float* __restrict__ wk,
             const float* __restrict__ wv)
{
    const int n = blockIdx.x;
    const int m = n >> 10;
    const int rem = n & 1023;
    const int h = rem >> 6, d = rem & 63;
    const int k = threadIdx.x;
    const float* w = (m == 0) ? wq : (m == 1) ? wk : wv;
    __half v = __float2half_rn(0.f);
    if ((k >> 6) == (h & 1)) {
        int q = k & 63;
        v = __float2half_rn(w[(q * 64 + d) * 16 + h]);
    }
    g_Wc2[(size_t)n * 128 + k] = v;
}

// =========================================================================
// Kernel 4: QKV projection v2 — one CTA computes Q, K AND V for one
// (o-slice, row-tile). X loaded once; W double-buffered. Warp tile 16x128
// keeps both RoPE partners in registers. V written DIRECTLY in original
// layout (c = d*16+h, aligned half2 pairs). grid (8, 128), 256 thr, 96KB.
// =========================================================================
__device__ __forceinline__ void proj_mma16(float acc[16][4], unsigned ab, unsigned bb,
                                           int a_row, int a_du, int b_row, int b_du,
                                           int lx)
{
#pragma unroll
    for (int kk = 0; kk < 8; kk++) {
        unsigned af[4], bf[16][2];
        ldsm4(af[0], af[1], af[2], af[3],
              ab + (unsigned)(a_row * 256 + (((2 * kk + a_du) ^ lx) << 4)));
#pragma unroll
        for (int p = 0; p < 8; p++)
            ldsm4(bf[2 * p][0], bf[2 * p][1], bf[2 * p + 1][0], bf[2 * p + 1][1],
                  bb + (unsigned)((b_row + 16 * p) * 256 + (((2 * kk + b_du) ^ lx) << 4)));
#pragma unroll
        for (int nt = 0; nt < 16; nt++) mma_f16(acc[nt], af, bf[nt]);
    }
}

__global__ void __launch_bounds__(256, 2)
proj_kernel()
{
    extern __shared__ __align__(128) char smc[];

    const int o = blockIdx.x * 128;        // channel slice (h0*64, h0 even)
    const int i0 = blockIdx.y * 128;       // global row
    const int hp = o >> 7;
    const int h0 = o >> 6;                 // even head

    const int tid = threadIdx.x;
    const int wid = tid >> 5, lane = tid & 31;
    const int group = lane >> 2, tid4 = lane & 3;

    const unsigned sb = (unsigned)__cvta_generic_to_shared(smc);

    // X tile + W0 -> group 0
#pragma unroll
    for (int l = 0; l < 8; l++) {
        int idx = tid + l * 256;
        int r = idx >> 4, u = idx & 15;
        int dst = r * 256 + ((u ^ (r & 7)) << 4);
        cpa16(smc + dst,         &g_Xh[(size_t)(i0 + r) * DM + o + u * 8]);
        cpa16(smc + 32768 + dst, &g_Wc2[(size_t)(o + r) * 128 + u * 8]);
    }
    cpa_commit();
    // W1 -> group 1
#pragma unroll
    for (int l = 0; l < 8; l++) {
        int idx = tid + l * 256;
        int r = idx >> 4, u = idx & 15;
        int dst = r * 256 + ((u ^ (r & 7)) << 4);
        cpa16(smc + 65536 + dst, &g_Wc2[(size_t)(1024 + o + r) * 128 + u * 8]);
    }
    cpa_commit();

    const int lx = lane & 7;
    const int a_row = (wid << 4) + (lane & 15);
    const int a_du = lane >> 4;
    const int b_row = (lane & 7) + ((lane >> 4) << 3);
    const int b_du = (lane >> 3) & 1;

    const int r0 = (wid << 4) + group;       // acc row (0..127), partner r0+8
    const size_t rowA = (size_t)(i0 + r0) * DM + o;
    const size_t rowB = (size_t)(i0 + r0 + 8) * DM + o;
    const float2* csA = g_cs + ((size_t)hp * T + ((i0 + r0) & (T - 1))) * 64;
    const float2* csB = g_cs + ((size_t)hp * T + ((i0 + r0 + 8) & (T - 1))) * 64;

    float acc[16][4];

    // ---- m = 0 (Q), W in buf0 ----
    cpa_wait<1>();
    __syncthreads();
#pragma unroll
    for (int nt = 0; nt < 16; nt++)
#pragma unroll
        for (int r = 0; r < 4; r++) acc[nt][r] = 0.f;
    proj_mma16(acc, sb, sb + 32768, a_row, a_du, b_row, b_du, lx);
    __syncthreads();                        // all reads of buf0 done
    // prefetch W2 -> buf0 (group 2)
#pragma unroll
    for (int l = 0; l < 8; l++) {
        int idx = tid + l * 256;
        int r = idx >> 4, u = idx & 15;
        int dst = r * 256 + ((u ^ (r & 7)) << 4);
        cpa16(smc + 32768 + dst, &g_Wc2[(size_t)(2048 + o + r) * 128 + u * 8]);
    }
    cpa_commit();
    // RoPE epilogue for Q
#pragma unroll
    for (int nt = 0; nt < 8; nt++) {
        int c = nt * 8 + tid4 * 2;
        float2 c0 = csA[c], c1 = csA[c + 1];
        float a0 = acc[nt][0], a1 = acc[nt][1];
        float b0 = acc[nt + 8][0], b1 = acc[nt + 8][1];
        *(__half2*)&g_Qh[rowA + c] =
            __floats2half2_rn(a0 * c0.x - b0 * c0.y, a1 * c1.x - b1 * c1.y);
        *(__half2*)&g_Qh[rowA + 64 + c] =
            __floats2half2_rn(a0 * c0.y + b0 * c0.x, a1 * c1.y + b1 * c1.x);
        float2 d0 = csB[c], d1 = csB[c + 1];
        float a2 = acc[nt][2], a3 = acc[nt][3];
        float b2 = acc[nt + 8][2], b3 = acc[nt + 8][3];
        *(__half2*)&g_Qh[rowB + c] =
            __floats2half2_rn(a2 * d0.x - b2 * d0.y, a3 * d1.x - b3 * d1.y);
        *(__half2*)&g_Qh[rowB + 64 + c] =
            __floats2half2_rn(a2 * d0.y + b2 * d0.x, a3 * d1.y + b3 * d1.x);
    }

    // ---- m = 1 (K), W in buf1 ----
    cpa_wait<1>();
    __syncthreads();
#pragma unroll
    for (int nt = 0; nt < 16; nt++)
#pragma unroll
        for (int r = 0; r < 4; r++) acc[nt][r] = 0.f;
    proj_mma16(acc, sb, sb + 65536, a_row, a_du, b_row, b_du, lx);
#pragma unroll
    for (int nt = 0; nt < 8; nt++) {
        int c = nt * 8 + tid4 * 2;
        float2 c0 = csA[c], c1 = csA[c + 1];
        float a0 = acc[nt][0], a1 = acc[nt][1];
        float b0 = acc[nt + 8][0], b1 = acc[nt + 8][1];
        *(__half2*)&g_Kh[rowA + c] =
            __floats2half2_rn(a0 * c0.x - b0 * c0.y, a1 * c1.x - b1 * c1.y);
        *(__half2*)&g_Kh[rowA + 64 + c] =
            __floats2half2_rn(a0 * c0.y + b0 * c0.x, a1 * c1.y + b1 * c1.x);
        float2 d0 = csB[c], d1 = csB[c + 1];
        float a2 = acc[nt][2], a3 = acc[nt][3];
        float b2 = acc[nt + 8][2], b3 = acc[nt + 8][3];
        *(__half2*)&g_Kh[rowB + c] =
            __floats2half2_rn(a2 * d0.x - b2 * d0.y, a3 * d1.x - b3 * d1.y);
        *(__half2*)&g_Kh[rowB + 64 + c] =
            __floats2half2_rn(a2 * d0.y + b2 * d0.x, a3 * d1.y + b3 * d1.x);
    }

    // ---- m = 2 (V), W in buf0 — write ORIGINAL layout directly ----
    cpa_wait<0>();
    __syncthreads();
#pragma unroll
    for (int nt = 0; nt < 16; nt++)
#pragma unroll
        for (int r = 0; r < 4; r++) acc[nt][r] = 0.f;
    proj_mma16(acc, sb, sb + 32768, a_row, a_du, b_row, b_du, lx);
    {
        const size_t vA = (size_t)(i0 + r0) * DM;
        const size_t vB = (size_t)(i0 + r0 + 8) * DM;
#pragma unroll
        for (int nt = 0; nt < 8; nt++) {
            int d = nt * 8 + tid4 * 2;
            // (head h0, head h0+1) at same d -> adjacent original channels
            *(__half2*)&g_Vh[vA + d * 16 + h0] =
                __floats2half2_rn(acc[nt][0], acc[nt + 8][0]);
            *(__half2*)&g_Vh[vA + (d + 1) * 16 + h0] =
                __floats2half2_rn(acc[nt][1], acc[nt + 8][1]);
            *(__half2*)&g_Vh[vB + d * 16 + h0] =
                __floats2half2_rn(acc[nt][2], acc[nt + 8][2]);
            *(__half2*)&g_Vh[vB + (d + 1) * 16 + h0] =
                __floats2half2_rn(acc[nt][3], acc[nt + 8][3]);
        }
    }
}

// =========================================================================
// Shared GEMM machinery (64-col K-chunks).
// =========================================================================
#define GK_STAGE_B 32768

__device__ __forceinline__ void gk_load(char* st, const __half* Ab, const __half* Bb,
                                        int kc, int tid)
{
#pragma unroll
    for (int l = 0; l < 4; l++) {
        int idx = tid + l * 256;
        int r = idx >> 3, u = idx & 7;
        int dst = r * 128 + ((u ^ (r & 7)) << 4);
        cpa16(st + dst,         &Ab[(size_t)r * DM + kc + u * 8]);
        cpa16(st + 16384 + dst, &Bb[(size_t)r * DM + kc + u * 8]);
    }
}

__device__ __forceinline__ void gk_mma(float acc[2][8][4], unsigned qb, unsigned kb,
                                       int m0, int n0, int lane)
{
    const int lx = lane & 7;
    const int a_row = m0 + (lane & 7) + (lane & 8);
    const int a_du = lane >> 4;
    const int b_row = n0 + (lane & 7) + ((lane >> 4) << 3);
    const int b_du = (lane >> 3) & 1;

#pragma unroll
    for (int kk = 0; kk < 4; kk++) {
        unsigned af[2][4], bf[8][2];
#pragma unroll
        for (int mt = 0; mt < 2; mt++)
            ldsm4(af[mt][0], af[mt][1], af[mt][2], af[mt][3],
                  qb + (unsigned)((a_row + mt * 16) * 128 + (((2 * kk + a_du) ^ lx) << 4)));
#pragma unroll
        for (int p = 0; p < 4; p++)
            ldsm4(bf[2 * p][0], bf[2 * p][1], bf[2 * p + 1][0], bf[2 * p + 1][1],
                  kb + (unsigned)((b_row + 16 * p) * 128 + (((2 * kk + b_du) ^ lx) << 4)));
#pragma unroll
        for (int mt = 0; mt < 2; mt++)
#pragma unroll
            for (int nt = 0; nt < 8; nt++) mma_f16(acc[mt][nt], af[mt], bf[nt]);
    }
}

// =========================================================================
// Kernel 5: P = exp(gamma * Q K^T) (causal), row sums via atomicAdd.
// grid (528, B), block 256, dyn smem 96KB
// =========================================================================
__global__ void __launch_bounds__(256, 2)
qk_kernel()
{
    extern __shared__ __align__(128) char smc[];

    const int b = blockIdx.y;
    const int xid = blockIdx.x;
    int ti = (int)((sqrtf(8.f * xid + 1.f) - 1.f) * 0.5f);
    while ((ti + 1) * (ti + 2) / 2 <= xid) ti++;
    while (ti * (ti + 1) / 2 > xid) ti--;
    const int tj = xid - ti * (ti + 1) / 2;
    const int i0 = ti * 128, j0 = tj * 128;

    const __half* Qb = g_Qh + (size_t)(b * T + i0) * DM;
    const __half* Kb = g_Kh + (size_t)(b * T + j0) * DM;

    const int tid = threadIdx.x;
    const int wid = tid >> 5, lane = tid & 31;
    const int group = lane >> 2, tid4 = lane & 3;
    const int m0 = (wid >> 1) * 32, n0 = (wid & 1) * 64;

    const unsigned sb = (unsigned)__cvta_generic_to_shared(smc);

    float acc[2][8][4];
#pragma unroll
    for (int mt = 0; mt < 2; mt++)
#pragma unroll
        for (int nt = 0; nt < 8; nt++)
#pragma unroll
            for (int r = 0; r < 4; r++) acc[mt][nt][r] = 0.f;

    const int NK = 16;
    gk_load(smc,              Qb, Kb, 0,  tid); cpa_commit();
    gk_load(smc + GK_STAGE_B, Qb, Kb, 64, tid); cpa_commit();

    for (int c = 0; c < NK; c++) {
        if (c + 1 < NK) { cpa_wait<1>(); } else { cpa_wait<0>(); }
        __syncthreads();
        if (c + 2 < NK) {
            gk_load(smc + ((c + 2) % 3) * GK_STAGE_B, Qb, Kb, (c + 2) * 64, tid);
            cpa_commit();
        }
        unsigned base = sb + (unsigned)((c % 3) * GK_STAGE_B);
        gk_mma(acc, base, base + 16384, m0, n0, lane);
    }

    const float GL = 0.03125f * 1.44269504f;
    const bool diag = (ti == tj);

#pragma unroll
    for (int mt = 0; mt < 2; mt++) {
        int rg = i0 + m0 + mt * 16 + group;
        float sum0 = 0.f, sum1 = 0.f;
#pragma unroll
        for (int nt = 0; nt < 8; nt++) {
            int cg = j0 + n0 + nt * 8 + tid4 * 2;
            float t0 = acc[mt][nt][0] * GL;
            float t1 = acc[mt][nt][1] * GL;
            float t2 = acc[mt][nt][2] * GL;
            float t3 = acc[mt][nt][3] * GL;
            if (diag) {
                if (cg     > rg)     t0 = -60000.f;
                if (cg + 1 > rg)     t1 = -60000.f;
                if (cg     > rg + 8) t2 = -60000.f;
                if (cg + 1 > rg + 8) t3 = -60000.f;
            }
            unsigned p01 = h2exp2(t0, t1);
            unsigned p23 = h2exp2(t2, t3);
            float2 f0 = __half22float2(*(__half2*)&p01);
            float2 f1 = __half22float2(*(__half2*)&p23);
            sum0 += f0.x + f0.y;
            sum1 += f1.x + f1.y;
            *(unsigned*)&g_Ph[(size_t)(b * T + rg) * T + cg]     = p01;
            *(unsigned*)&g_Ph[(size_t)(b * T + rg + 8) * T + cg] = p23;
        }
        sum0 += __shfl_xor_sync(0xffffffffu, sum0, 1);
        sum0 += __shfl_xor_sync(0xffffffffu, sum0, 2);
        sum1 += __shfl_xor_sync(0xffffffffu, sum1, 1);
        sum1 += __shfl_xor_sync(0xffffffffu, sum1, 2);
        if (tid4 == 0) {
            atomicAdd(&g_Sum[b * T + rg],     sum0);
            atomicAdd(&g_Sum[b * T + rg + 8], sum1);
        }
    }
}

// =========================================================================
// Kernel 6: Y = (P V) / g_Sum[row] — heavy m-tiles scheduled FIRST.
// grid (8 n-tiles, 32 m-tiles, B), block 256, dyn smem 96KB
// =========================================================================
#define PV_STAGE_B 32768

__device__ __forceinline__ void pv_load(char* st, const __half* Pb, const __half* Vb,
                                        int kc, int tid)
{
#pragma unroll
    for (int l = 0; l < 4; l++) {
        int idx = tid + l * 256;
        {
            int r = idx >> 3, u = idx & 7;
            cpa16(st + r * 128 + ((u ^ (r & 7)) << 4),
                  &Pb[(size_t)r * T + kc + u * 8]);
        }
        {
            int r = idx >> 4, u = idx & 15;
            cpa16(st + 16384 + r * 256 + ((u ^ (r & 7)) << 4),
                  &Vb[(size_t)(kc + r) * DM + u * 8]);
        }
    }
}

__device__ __forceinline__ void pv_mma(float acc[2][8][4], unsigned pb, unsigned vb,
                                       int m0, int n0, int lane)
{
    const int lx = lane & 7;
    const int a_row = m0 + (lane & 7) + (lane & 8);
    const int a_du = lane >> 4;
    const int v_row = (lane & 7) + (lane & 8);
    const int v_du = lane >> 4;
    const int un0 = n0 >> 3;

#pragma unroll
    for (int kk = 0; kk < 4; kk++) {
        unsigned af[2][4], bf[8][2];
#pragma unroll
        for (int mt = 0; mt < 2; mt++)
            ldsm4(af[mt][0], af[mt][1], af[mt][2], af[mt][3],
                  pb + (unsigned)((a_row + mt * 16) * 128 + (((2 * kk + a_du) ^ lx) << 4)));
        const int vr = 16 * kk + v_row;
#pragma unroll
        for (int p = 0; p < 4; p++)
            ldsm4t(bf[2 * p][0], bf[2 * p][1], bf[2 * p + 1][0], bf[2 * p + 1][1],
                   vb + (unsigned)(vr * 256 + (((un0 + 2 * p + v_du) ^ lx) << 4)));
#pragma unroll
        for (int mt = 0; mt < 2; mt++)
#pragma unroll
            for (int nt = 0; nt < 8; nt++) mma_f16(acc[mt][nt], af[mt], bf[nt]);
    }
}

__global__ void __launch_bounds__(256, 2)
pv_kernel(float* __restrict__ out)
{
    extern __shared__ __align__(128) char smc[];

    const int b = blockIdx.z, ni = blockIdx.x;
    const int mi = gridDim.y - 1 - blockIdx.y;   // heavy tiles first
    const int i0 = mi * 128, n0c = ni * 128;

    const int tid = threadIdx.x;
    const int wid = tid >> 5, lane = tid & 31;
    const int group = lane >> 2, tid4 = lane & 3;
    const int m0 = (wid >> 1) * 32, n0 = (wid & 1) * 64;

    const __half* Pb = g_Ph + (size_t)(b * T + i0) * T;
    const __half* Vb = g_Vh + (size_t)(b * T) * DM + n0c;

    const unsigned sb = (unsigned)__cvta_generic_to_shared(smc);

    float acc[2][8][4];
#pragma unroll
    for (int mt = 0; mt < 2; mt++)
#pragma unroll
        for (int nt = 0; nt < 8; nt++)
#pragma unroll
            for (int r = 0; r < 4; r++) acc[mt][nt][r] = 0.f;

    const int nk = (mi + 1) * 2;

    pv_load(smc,              Pb, Vb, 0,  tid); cpa_commit();
    pv_load(smc + PV_STAGE_B, Pb, Vb, 64, tid); cpa_commit();

    for (int c = 0; c < nk; c++) {
        if (c + 1 < nk) { cpa_wait<1>(); } else { cpa_wait<0>(); }
        __syncthreads();
        if (c + 2 < nk) {
            pv_load(smc + ((c + 2) % 3) * PV_STAGE_B, Pb, Vb, (c + 2) * 64, tid);
            cpa_commit();
        }
        unsigned base = sb + (unsigned)((c % 3) * PV_STAGE_B);
        pv_mma(acc, base, base + 16384, m0, n0, lane);
    }

    const float* sump = g_Sum + (size_t)b * T + i0;
#pragma unroll
    for (int mt = 0; mt < 2; mt++) {
        int rloc = m0 + mt * 16 + group;
        float inva = 1.f / sump[rloc];
        float invb = 1.f / sump[rloc + 8];
#pragma unroll
        for (int nt = 0; nt < 8; nt++) {
            int rg = i0 + rloc;
            int cg = n0c + n0 + nt * 8 + tid4 * 2;
            *(float2*)&out[(size_t)(b * T + rg) * DM + cg] =
                make_float2(acc[mt][nt][0] * inva, acc[mt][nt][1] * inva);
            *(float2*)&out[(size_t)(b * T + rg + 8) * DM + cg] =
                make_float2(acc[mt][nt][2] * invb, acc[mt][nt][3] * invb);
        }
    }
}

// =========================================================================
extern "C" void kernel_launch(void* const* d_in, const int* in_sizes, int n_in,
                              void* d_out, int out_size)
{
    const float* x  = (const float*)d_in[0];
    const float* wq = (const float*)d_in[1];
    const float* wk = (const float*)d_in[2];
    const float* wv = (const float*)d_in[3];
    float* out = (float*)d_out;

    cudaFuncSetAttribute(proj_kernel,
                         cudaFuncAttributeMaxDynamicSharedMemorySize, 98304);
    cudaFuncSetAttribute(qk_kernel,
                         cudaFuncAttributeMaxDynamicSharedMemorySize, 3 * GK_STAGE_B);
    cudaFuncSetAttribute(pv_kernel,
                         cudaFuncAttributeMaxDynamicSharedMemorySize, 3 * PV_STAGE_B);

    permute_kernel<<<4096, 256>>>(x);
    table_kernel<<<T, 512>>>();
    fillw_kernel<<<NOUT, 128>>>(wq, wk, wv);
    proj_kernel<<<dim3(8, 128), 256, 98304>>>();
    qk_kernel<<<dim3(528, BB), 256, 3 * GK_STAGE_B>>>();
    pv_kernel<<<dim3(8, 32, BB), 256, 3 * PV_STAGE_B>>>(out);
}

// round 16
// speedup vs baseline: 1.5313x; 1.0660x over previous
#include <cuda_runtime.h>
#include <cuda_fp16.h>
#include <math.h>

#define BB 4
#define T 4096
#define DM 1024
#define NROWS (BB * T)          // 16384
#define NOUT (3 * DM)           // 3072

// ---------------- scratch ----------------
__device__ __half g_Xh[(size_t)NROWS * DM];        // fp16 input, PERMUTED c' = h*64+q
__device__ __half g_Wc2[(size_t)NOUT * 128];       // compact block-diag weights
__device__ __half g_Qh[(size_t)NROWS * DM];        // permuted c' = h*64+d
__device__ __half g_Kh[(size_t)NROWS * DM];        // permuted
__device__ __half g_Vp[(size_t)NROWS * DM];        // V permuted (proj output)
__device__ __half g_Vh[(size_t)NROWS * DM];        // V ORIGINAL layout c = d*16+h
__device__ __half g_Ph[(size_t)BB * T * T];        // fp16 unnormalized probs
__device__ float  g_Sum[NROWS];                    // row sums of exp(s)
__device__ float  g_invf[512];                     // rope inverse frequencies
__device__ float2 g_cs[(size_t)8 * T * 64];        // [hp][t][d] (cos,sin)

// ---------------- helpers ----------------
__device__ __forceinline__ unsigned h2exp2(float lo, float hi) {
    unsigned d, r;
    asm("cvt.rn.f16x2.f32 %0, %1, %2;" : "=r"(d) : "f"(hi), "f"(lo));
    asm("ex2.approx.f16x2 %0, %1;" : "=r"(r) : "r"(d));
    return r;
}

__device__ __forceinline__ void cpa16(void* dst, const void* src) {
    unsigned d = (unsigned)__cvta_generic_to_shared(dst);
    asm volatile("cp.async.cg.shared.global [%0], [%1], 16;" :: "r"(d), "l"(src));
}
__device__ __forceinline__ void cpa_commit() {
    asm volatile("cp.async.commit_group;" ::: "memory");
}
template <int N>
__device__ __forceinline__ void cpa_wait() {
    asm volatile("cp.async.wait_group %0;" :: "n"(N) : "memory");
}

__device__ __forceinline__ void ldsm4(unsigned& r0, unsigned& r1, unsigned& r2,
                                      unsigned& r3, unsigned addr) {
    asm volatile("ldmatrix.sync.aligned.m8n8.x4.shared.b16 {%0,%1,%2,%3}, [%4];"
        : "=r"(r0), "=r"(r1), "=r"(r2), "=r"(r3) : "r"(addr));
}
__device__ __forceinline__ void ldsm4t(unsigned& r0, unsigned& r1, unsigned& r2,
                                       unsigned& r3, unsigned addr) {
    asm volatile("ldmatrix.sync.aligned.m8n8.x4.trans.shared.b16 {%0,%1,%2,%3}, [%4];"
        : "=r"(r0), "=r"(r1), "=r"(r2), "=r"(r3) : "r"(addr));
}

__device__ __forceinline__ void mma_f16(float* c, const unsigned* a, const unsigned* b) {
    asm volatile(
        "mma.sync.aligned.m16n8k16.row.col.f32.f16.f16.f32 "
        "{%0,%1,%2,%3}, {%4,%5,%6,%7}, {%8,%9}, {%0,%1,%2,%3};\n"
        : "+f"(c[0]), "+f"(c[1]), "+f"(c[2]), "+f"(c[3])
        : "r"(a[0]), "r"(a[1]), "r"(a[2]), "r"(a[3]), "r"(b[0]), "r"(b[1]));
}

#define PXS(a) ((a) ^ (((a) >> 5) & 28))   // smem swizzle for permute

// =========================================================================
// Kernel 1: permute x -> fp16 head-major (c' = h*64+q), init g_Sum, g_invf.
// =========================================================================
__global__ void __launch_bounds__(256)
permute_kernel(const float* __restrict__ x)
{
    __shared__ float sm[4][1024];
    const int row0 = blockIdx.x * 4;
    const int tid = threadIdx.x;
    const int c = tid * 4;

#pragma unroll
    for (int rr = 0; rr < 4; rr++)
        *(float4*)&sm[rr][PXS(c)] = *(const float4*)&x[(size_t)(row0 + rr) * DM + c];
    __syncthreads();

    const int h = c >> 6, q = c & 63;
#pragma unroll
    for (int rr = 0; rr < 4; rr++) {
        float v0 = sm[rr][PXS(q * 16 + h)];
        float v1 = sm[rr][PXS((q + 1) * 16 + h)];
        float v2 = sm[rr][PXS((q + 2) * 16 + h)];
        float v3 = sm[rr][PXS((q + 3) * 16 + h)];
        __half2 h0 = __floats2half2_rn(v0, v1);
        __half2 h1 = __floats2half2_rn(v2, v3);
        uint2 pk;
        pk.x = *(unsigned*)&h0;
        pk.y = *(unsigned*)&h1;
        *(uint2*)&g_Xh[(size_t)(row0 + rr) * DM + c] = pk;
    }
    if (tid < 4) g_Sum[row0 + tid] = 0.f;
    if (blockIdx.x == 0) {
        g_invf[tid]       = (float)pow(10000.0, -(double)tid / 512.0);
        g_invf[tid + 256] = (float)pow(10000.0, -(double)(tid + 256) / 512.0);
    }
}

// =========================================================================
// Kernel 2: cos/sin table, layout [hp][t][d]. grid T, block 512.
// =========================================================================
__global__ void __launch_bounds__(512)
table_kernel()
{
    const int t = blockIdx.x;
    const int i = threadIdx.x;
    const int hp = i >> 6, d = i & 63;
    const int p = d * 8 + hp;
    float s, c;
    sincosf((float)t * g_invf[p], &s, &c);
    g_cs[((size_t)hp * T + t) * 64 + d] = make_float2(c, s);
}

// =========================================================================
// Kernel 3: compact block-diag weights Wc2[n''][128].
// =========================================================================
__global__ void __launch_bounds__(128)
fillw_kernel(const float* __restrict__ wq,
             const float* __restrict__ wk,
             const float* __restrict__ wv)
{
    const int n = blockIdx.x;
    const int m = n >> 10;
    const int rem = n & 1023;
    const int h = rem >> 6, d = rem & 63;
    const int k = threadIdx.x;
    const float* w = (m == 0) ? wq : (m == 1) ? wk : wv;
    __half v = __float2half_rn(0.f);
    if ((k >> 6) == (h & 1)) {
        int q = k & 63;
        v = __float2half_rn(w[(q * 64 + d) * 16 + h]);
    }
    g_Wc2[(size_t)n * 128 + k] = v;
}

// =========================================================================
// Kernel 4: QKV projection v2 (r13 exact) — one CTA computes Q, K, V for
// one (o-slice, row-tile); W double-buffered; register RoPE; float2 cs.
// grid (8, 128), block 256, dyn smem 96KB.
// =========================================================================
__device__ __forceinline__ void proj_mma16(float acc[16][4], unsigned ab, unsigned bb,
                                           int a_row, int a_du, int b_row, int b_du,
                                           int lx)
{
#pragma unroll
    for (int kk = 0; kk < 8; kk++) {
        unsigned af[4], bf[16][2];
        ldsm4(af[0], af[1], af[2], af[3],
              ab + (unsigned)(a_row * 256 + (((2 * kk + a_du) ^ lx) << 4)));
#pragma unroll
        for (int p = 0; p < 8; p++)
            ldsm4(bf[2 * p][0], bf[2 * p][1], bf[2 * p + 1][0], bf[2 * p + 1][1],
                  bb + (unsigned)((b_row + 16 * p) * 256 + (((2 * kk + b_du) ^ lx) << 4)));
#pragma unroll
        for (int nt = 0; nt < 16; nt++) mma_f16(acc[nt], af, bf[nt]);
    }
}

__global__ void __launch_bounds__(256, 2)
proj_kernel()
{
    extern __shared__ __align__(128) char smc[];

    const int o = blockIdx.x * 128;
    const int i0 = blockIdx.y * 128;
    const int hp = o >> 7;

    const int tid = threadIdx.x;
    const int wid = tid >> 5, lane = tid & 31;
    const int group = lane >> 2, tid4 = lane & 3;

    const unsigned sb = (unsigned)__cvta_generic_to_shared(smc);

#pragma unroll
    for (int l = 0; l < 8; l++) {
        int idx = tid + l * 256;
        int r = idx >> 4, u = idx & 15;
        int dst = r * 256 + ((u ^ (r & 7)) << 4);
        cpa16(smc + dst,         &g_Xh[(size_t)(i0 + r) * DM + o + u * 8]);
        cpa16(smc + 32768 + dst, &g_Wc2[(size_t)(o + r) * 128 + u * 8]);
    }
    cpa_commit();
#pragma unroll
    for (int l = 0; l < 8; l++) {
        int idx = tid + l * 256;
        int r = idx >> 4, u = idx & 15;
        int dst = r * 256 + ((u ^ (r & 7)) << 4);
        cpa16(smc + 65536 + dst, &g_Wc2[(size_t)(1024 + o + r) * 128 + u * 8]);
    }
    cpa_commit();

    const int lx = lane & 7;
    const int a_row = (wid << 4) + (lane & 15);
    const int a_du = lane >> 4;
    const int b_row = (lane & 7) + ((lane >> 4) << 3);
    const int b_du = (lane >> 3) & 1;

    const int r0 = (wid << 4) + group;
    const size_t rowA = (size_t)(i0 + r0) * DM + o;
    const size_t rowB = (size_t)(i0 + r0 + 8) * DM + o;
    const float2* csA = g_cs + ((size_t)hp * T + ((i0 + r0) & (T - 1))) * 64;
    const float2* csB = g_cs + ((size_t)hp * T + ((i0 + r0 + 8) & (T - 1))) * 64;

    float acc[16][4];

    // ---- m = 0 (Q), W in buf0 ----
    cpa_wait<1>();
    __syncthreads();
#pragma unroll
    for (int nt = 0; nt < 16; nt++)
#pragma unroll
        for (int r = 0; r < 4; r++) acc[nt][r] = 0.f;
    proj_mma16(acc, sb, sb + 32768, a_row, a_du, b_row, b_du, lx);
    __syncthreads();
#pragma unroll
    for (int l = 0; l < 8; l++) {
        int idx = tid + l * 256;
        int r = idx >> 4, u = idx & 15;
        int dst = r * 256 + ((u ^ (r & 7)) << 4);
        cpa16(smc + 32768 + dst, &g_Wc2[(size_t)(2048 + o + r) * 128 + u * 8]);
    }
    cpa_commit();
#pragma unroll
    for (int nt = 0; nt < 8; nt++) {
        int c = nt * 8 + tid4 * 2;
        float2 c0 = csA[c], c1 = csA[c + 1];
        float a0 = acc[nt][0], a1 = acc[nt][1];
        float b0 = acc[nt + 8][0], b1 = acc[nt + 8][1];
        *(__half2*)&g_Qh[rowA + c] =
            __floats2half2_rn(a0 * c0.x - b0 * c0.y, a1 * c1.x - b1 * c1.y);
        *(__half2*)&g_Qh[rowA + 64 + c] =
            __floats2half2_rn(a0 * c0.y + b0 * c0.x, a1 * c1.y + b1 * c1.x);
        float2 d0 = csB[c], d1 = csB[c + 1];
        float a2 = acc[nt][2], a3 = acc[nt][3];
        float b2 = acc[nt + 8][2], b3 = acc[nt + 8][3];
        *(__half2*)&g_Qh[rowB + c] =
            __floats2half2_rn(a2 * d0.x - b2 * d0.y, a3 * d1.x - b3 * d1.y);
        *(__half2*)&g_Qh[rowB + 64 + c] =
            __floats2half2_rn(a2 * d0.y + b2 * d0.x, a3 * d1.y + b3 * d1.x);
    }

    // ---- m = 1 (K), W in buf1 ----
    cpa_wait<1>();
    __syncthreads();
#pragma unroll
    for (int nt = 0; nt < 16; nt++)
#pragma unroll
        for (int r = 0; r < 4; r++) acc[nt][r] = 0.f;
    proj_mma16(acc, sb, sb + 65536, a_row, a_du, b_row, b_du, lx);
#pragma unroll
    for (int nt = 0; nt < 8; nt++) {
        int c = nt * 8 + tid4 * 2;
        float2 c0 = csA[c], c1 = csA[c + 1];
        float a0 = acc[nt][0], a1 = acc[nt][1];
        float b0 = acc[nt + 8][0], b1 = acc[nt + 8][1];
        *(__half2*)&g_Kh[rowA + c] =
            __floats2half2_rn(a0 * c0.x - b0 * c0.y, a1 * c1.x - b1 * c1.y);
        *(__half2*)&g_Kh[rowA + 64 + c] =
            __floats2half2_rn(a0 * c0.y + b0 * c0.x, a1 * c1.y + b1 * c1.x);
        float2 d0 = csB[c], d1 = csB[c + 1];
        float a2 = acc[nt][2], a3 = acc[nt][3];
        float b2 = acc[nt + 8][2], b3 = acc[nt + 8][3];
        *(__half2*)&g_Kh[rowB + c] =
            __floats2half2_rn(a2 * d0.x - b2 * d0.y, a3 * d1.x - b3 * d1.y);
        *(__half2*)&g_Kh[rowB + 64 + c] =
            __floats2half2_rn(a2 * d0.y + b2 * d0.x, a3 * d1.y + b3 * d1.x);
    }

    // ---- m = 2 (V), W in buf0 ----
    cpa_wait<0>();
    __syncthreads();
#pragma unroll
    for (int nt = 0; nt < 16; nt++)
#pragma unroll
        for (int r = 0; r < 4; r++) acc[nt][r] = 0.f;
    proj_mma16(acc, sb, sb + 32768, a_row, a_du, b_row, b_du, lx);
#pragma unroll
    for (int nt = 0; nt < 8; nt++) {
        int c = nt * 8 + tid4 * 2;
        *(__half2*)&g_Vp[rowA + c]      = __floats2half2_rn(acc[nt][0], acc[nt][1]);
        *(__half2*)&g_Vp[rowA + 64 + c] = __floats2half2_rn(acc[nt + 8][0], acc[nt + 8][1]);
        *(__half2*)&g_Vp[rowB + c]      = __floats2half2_rn(acc[nt][2], acc[nt][3]);
        *(__half2*)&g_Vp[rowB + 64 + c] = __floats2half2_rn(acc[nt + 8][2], acc[nt + 8][3]);
    }
}

// =========================================================================
// Kernel 4b: V layout transform  c'=h*64+d  ->  c=d*16+h.
// =========================================================================
__global__ void __launch_bounds__(256)
vtrans_kernel()
{
    __shared__ __half sm[8][1092];
    const int r0 = blockIdx.x * 8;
    const int tid = threadIdx.x;

#pragma unroll
    for (int k = 0; k < 16; k++) {
        int idx = k * 256 + tid;
        int rr = idx >> 9;
        int ui = idx & 511;
        unsigned v = ((const unsigned*)&g_Vp[(size_t)(r0 + rr) * DM])[ui];
        int h = ui >> 5;
        int dw = ui & 31;
        ((unsigned*)&sm[rr][h * 68])[dw] = v;
    }
    __syncthreads();

#pragma unroll
    for (int k = 0; k < 16; k++) {
        int idx = k * 256 + tid;
        int rr = idx >> 9;
        int j = idx & 511;
        int c = j * 2;
        int h0 = c & 15,      d0 = c >> 4;
        int h1 = (c + 1) & 15, d1 = (c + 1) >> 4;
        __half lo = sm[rr][h0 * 68 + d0];
        __half hi = sm[rr][h1 * 68 + d1];
        *(__half2*)&g_Vh[(size_t)(r0 + rr) * DM + c] = __halves2half2(lo, hi);
    }
}

// =========================================================================
// Shared GEMM machinery (64-col K-chunks).
// =========================================================================
#define GK_STAGE_B 32768

__device__ __forceinline__ void gk_load(char* st, const __half* Ab, const __half* Bb,
                                        int kc, int tid)
{
#pragma unroll
    for (int l = 0; l < 4; l++) {
        int idx = tid + l * 256;
        int r = idx >> 3, u = idx & 7;
        int dst = r * 128 + ((u ^ (r & 7)) << 4);
        cpa16(st + dst,         &Ab[(size_t)r * DM + kc + u * 8]);
        cpa16(st + 16384 + dst, &Bb[(size_t)r * DM + kc + u * 8]);
    }
}

__device__ __forceinline__ void gk_mma(float acc[2][8][4], unsigned qb, unsigned kb,
                                       int m0, int n0, int lane)
{
    const int lx = lane & 7;
    const int a_row = m0 + (lane & 7) + (lane & 8);
    const int a_du = lane >> 4;
    const int b_row = n0 + (lane & 7) + ((lane >> 4) << 3);
    const int b_du = (lane >> 3) & 1;

#pragma unroll
    for (int kk = 0; kk < 4; kk++) {
        unsigned af[2][4], bf[8][2];
#pragma unroll
        for (int mt = 0; mt < 2; mt++)
            ldsm4(af[mt][0], af[mt][1], af[mt][2], af[mt][3],
                  qb + (unsigned)((a_row + mt * 16) * 128 + (((2 * kk + a_du) ^ lx) << 4)));
#pragma unroll
        for (int p = 0; p < 4; p++)
            ldsm4(bf[2 * p][0], bf[2 * p][1], bf[2 * p + 1][0], bf[2 * p + 1][1],
                  kb + (unsigned)((b_row + 16 * p) * 128 + (((2 * kk + b_du) ^ lx) << 4)));
#pragma unroll
        for (int mt = 0; mt < 2; mt++)
#pragma unroll
            for (int nt = 0; nt < 8; nt++) mma_f16(acc[mt][nt], af[mt], bf[nt]);
    }
}

// =========================================================================
// Kernel 5: P = exp(gamma * Q K^T) (causal), row sums via atomicAdd.
// grid (528, B), block 256, dyn smem 96KB
// =========================================================================
__global__ void __launch_bounds__(256, 2)
qk_kernel()
{
    extern __shared__ __align__(128) char smc[];

    const int b = blockIdx.y;
    const int xid = blockIdx.x;
    int ti = (int)((sqrtf(8.f * xid + 1.f) - 1.f) * 0.5f);
    while ((ti + 1) * (ti + 2) / 2 <= xid) ti++;
    while (ti * (ti + 1) / 2 > xid) ti--;
    const int tj = xid - ti * (ti + 1) / 2;
    const int i0 = ti * 128, j0 = tj * 128;

    const __half* Qb = g_Qh + (size_t)(b * T + i0) * DM;
    const __half* Kb = g_Kh + (size_t)(b * T + j0) * DM;

    const int tid = threadIdx.x;
    const int wid = tid >> 5, lane = tid & 31;
    const int group = lane >> 2, tid4 = lane & 3;
    const int m0 = (wid >> 1) * 32, n0 = (wid & 1) * 64;

    const unsigned sb = (unsigned)__cvta_generic_to_shared(smc);

    float acc[2][8][4];
#pragma unroll
    for (int mt = 0; mt < 2; mt++)
#pragma unroll
        for (int nt = 0; nt < 8; nt++)
#pragma unroll
            for (int r = 0; r < 4; r++) acc[mt][nt][r] = 0.f;

    const int NK = 16;
    gk_load(smc,              Qb, Kb, 0,  tid); cpa_commit();
    gk_load(smc + GK_STAGE_B, Qb, Kb, 64, tid); cpa_commit();

    for (int c = 0; c < NK; c++) {
        if (c + 1 < NK) { cpa_wait<1>(); } else { cpa_wait<0>(); }
        __syncthreads();
        if (c + 2 < NK) {
            gk_load(smc + ((c + 2) % 3) * GK_STAGE_B, Qb, Kb, (c + 2) * 64, tid);
            cpa_commit();
        }
        unsigned base = sb + (unsigned)((c % 3) * GK_STAGE_B);
        gk_mma(acc, base, base + 16384, m0, n0, lane);
    }

    const float GL = 0.03125f * 1.44269504f;
    const bool diag = (ti == tj);

#pragma unroll
    for (int mt = 0; mt < 2; mt++) {
        int rg = i0 + m0 + mt * 16 + group;
        float sum0 = 0.f, sum1 = 0.f;
#pragma unroll
        for (int nt = 0; nt < 8; nt++) {
            int cg = j0 + n0 + nt * 8 + tid4 * 2;
            float t0 = acc[mt][nt][0] * GL;
            float t1 = acc[mt][nt][1] * GL;
            float t2 = acc[mt][nt][2] * GL;
            float t3 = acc[mt][nt][3] * GL;
            if (diag) {
                if (cg     > rg)     t0 = -60000.f;
                if (cg + 1 > rg)     t1 = -60000.f;
                if (cg     > rg + 8) t2 = -60000.f;
                if (cg + 1 > rg + 8) t3 = -60000.f;
            }
            unsigned p01 = h2exp2(t0, t1);
            unsigned p23 = h2exp2(t2, t3);
            float2 f0 = __half22float2(*(__half2*)&p01);
            float2 f1 = __half22float2(*(__half2*)&p23);
            sum0 += f0.x + f0.y;
            sum1 += f1.x + f1.y;
            *(unsigned*)&g_Ph[(size_t)(b * T + rg) * T + cg]     = p01;
            *(unsigned*)&g_Ph[(size_t)(b * T + rg + 8) * T + cg] = p23;
        }
        sum0 += __shfl_xor_sync(0xffffffffu, sum0, 1);
        sum0 += __shfl_xor_sync(0xffffffffu, sum0, 2);
        sum1 += __shfl_xor_sync(0xffffffffu, sum1, 1);
        sum1 += __shfl_xor_sync(0xffffffffu, sum1, 2);
        if (tid4 == 0) {
            atomicAdd(&g_Sum[b * T + rg],     sum0);
            atomicAdd(&g_Sum[b * T + rg + 8], sum1);
        }
    }
}

// =========================================================================
// Kernel 6: Y = (P V) / g_Sum[row] — TRUE LPT order: mi descending in the
// OUTERMOST grid dim (z), so the heaviest tiles across all batches launch
// first. grid (8 n-tiles, B, 32 mi-slots), block 256, dyn smem 96KB.
// =========================================================================
#define PV_STAGE_B 32768

__device__ __forceinline__ void pv_load(char* st, const __half* Pb, const __half* Vb,
                                        int kc, int tid)
{
#pragma unroll
    for (int l = 0; l < 4; l++) {
        int idx = tid + l * 256;
        {
            int r = idx >> 3, u = idx & 7;
            cpa16(st + r * 128 + ((u ^ (r & 7)) << 4),
                  &Pb[(size_t)r * T + kc + u * 8]);
        }
        {
            int r = idx >> 4, u = idx & 15;
            cpa16(st + 16384 + r * 256 + ((u ^ (r & 7)) << 4),
                  &Vb[(size_t)(kc + r) * DM + u * 8]);
        }
    }
}

__device__ __forceinline__ void pv_mma(float acc[2][8][4], unsigned pb, unsigned vb,
                                       int m0, int n0, int lane)
{
    const int lx = lane & 7;
    const int a_row = m0 + (lane & 7) + (lane & 8);
    const int a_du = lane >> 4;
    const int v_row = (lane & 7) + (lane & 8);
    const int v_du = lane >> 4;
    const int un0 = n0 >> 3;

#pragma unroll
    for (int kk = 0; kk < 4; kk++) {
        unsigned af[2][4], bf[8][2];
#pragma unroll
        for (int mt = 0; mt < 2; mt++)
            ldsm4(af[mt][0], af[mt][1], af[mt][2], af[mt][3],
                  pb + (unsigned)((a_row + mt * 16) * 128 + (((2 * kk + a_du) ^ lx) << 4)));
        const int vr = 16 * kk + v_row;
#pragma unroll
        for (int p = 0; p < 4; p++)
            ldsm4t(bf[2 * p][0], bf[2 * p][1], bf[2 * p + 1][0], bf[2 * p + 1][1],
                   vb + (unsigned)(vr * 256 + (((un0 + 2 * p + v_du) ^ lx) << 4)));
#pragma unroll
        for (int mt = 0; mt < 2; mt++)
#pragma unroll
            for (int nt = 0; nt < 8; nt++) mma_f16(acc[mt][nt], af[mt], bf[nt]);
    }
}

__global__ void __launch_bounds__(256, 2)
pv_kernel(float* __restrict__ out)
{
    extern __shared__ __align__(128) char smc[];

    const int ni = blockIdx.x;
    const int b = blockIdx.y;
    const int mi = 31 - blockIdx.z;              // heaviest first, across batches
    const int i0 = mi * 128, n0c = ni * 128;

    const int tid = threadIdx.x;
    const int wid = tid >> 5, lane = tid & 31;
    const int group = lane >> 2, tid4 = lane & 3;
    const int m0 = (wid >> 1) * 32, n0 = (wid & 1) * 64;

    const __half* Pb = g_Ph + (size_t)(b * T + i0) * T;
    const __half* Vb = g_Vh + (size_t)(b * T) * DM + n0c;

    const unsigned sb = (unsigned)__cvta_generic_to_shared(smc);

    float acc[2][8][4];
#pragma unroll
    for (int mt = 0; mt < 2; mt++)
#pragma unroll
        for (int nt = 0; nt < 8; nt++)
#pragma unroll
            for (int r = 0; r < 4; r++) acc[mt][nt][r] = 0.f;

    const int nk = (mi + 1) * 2;

    pv_load(smc,              Pb, Vb, 0,  tid); cpa_commit();
    pv_load(smc + PV_STAGE_B, Pb, Vb, 64, tid); cpa_commit();

    for (int c = 0; c < nk; c++) {
        if (c + 1 < nk) { cpa_wait<1>(); } else { cpa_wait<0>(); }
        __syncthreads();
        if (c + 2 < nk) {
            pv_load(smc + ((c + 2) % 3) * PV_STAGE_B, Pb, Vb, (c + 2) * 64, tid);
            cpa_commit();
        }
        unsigned base = sb + (unsigned)((c % 3) * PV_STAGE_B);
        pv_mma(acc, base, base + 16384, m0, n0, lane);
    }

    const float* sump = g_Sum + (size_t)b * T + i0;
#pragma unroll
    for (int mt = 0; mt < 2; mt++) {
        int rloc = m0 + mt * 16 + group;
        float inva = 1.f / sump[rloc];
        float invb = 1.f / sump[rloc + 8];
#pragma unroll
        for (int nt = 0; nt < 8; nt++) {
            int rg = i0 + rloc;
            int cg = n0c + n0 + nt * 8 + tid4 * 2;
            *(float2*)&out[(size_t)(b * T + rg) * DM + cg] =
                make_float2(acc[mt][nt][0] * inva, acc[mt][nt][1] * inva);
            *(float2*)&out[(size_t)(b * T + rg + 8) * DM + cg] =
                make_float2(acc[mt][nt][2] * invb, acc[mt][nt][3] * invb);
        }
    }
}

// =========================================================================
extern "C" void kernel_launch(void* const* d_in, const int* in_sizes, int n_in,
                              void* d_out, int out_size)
{
    const float* x  = (const float*)d_in[0];
    const float* wq = (const float*)d_in[1];
    const float* wk = (const float*)d_in[2];
    const float* wv = (const float*)d_in[3];
    float* out = (float*)d_out;

    cudaFuncSetAttribute(proj_kernel,
                         cudaFuncAttributeMaxDynamicSharedMemorySize, 98304);
    cudaFuncSetAttribute(qk_kernel,
                         cudaFuncAttributeMaxDynamicSharedMemorySize, 3 * GK_STAGE_B);
    cudaFuncSetAttribute(pv_kernel,
                         cudaFuncAttributeMaxDynamicSharedMemorySize, 3 * PV_STAGE_B);

    permute_kernel<<<4096, 256>>>(x);
    table_kernel<<<T, 512>>>();
    fillw_kernel<<<NOUT, 128>>>(wq, wk, wv);
    proj_kernel<<<dim3(8, 128), 256, 98304>>>();
    vtrans_kernel<<<NROWS / 8, 256>>>();
    qk_kernel<<<dim3(528, BB), 256, 3 * GK_STAGE_B>>>();
    pv_kernel<<<dim3(8, BB, 32), 256, 3 * PV_STAGE_B>>>(out);
}